// round 1
// baseline (speedup 1.0000x reference)
#include <cuda_runtime.h>
#include <math_constants.h>

// Scratch (no dynamic allocation allowed): pooled x4 and combined pool(x3)+pool(x4).
__device__ float g_P4[2 * 256];
__device__ float g_T3[2 * 256 * 256];

// ---------------------------------------------------------------------------
// Kernel 0: P4[b, hw] = maxpool16(x4[b,0])   (x4: [2,1,256,256])
// grid = 2 blocks, 256 threads; thread t -> (oh, ow) = (t/16, t%16)
// ---------------------------------------------------------------------------
__global__ void pool_x4_kernel(const float* __restrict__ x4) {
    const int b  = blockIdx.x;
    const int t  = threadIdx.x;
    const int oh = t >> 4, ow = t & 15;
    const float* base = x4 + (size_t)b * 65536;
    float m = -CUDART_INF_F;
#pragma unroll
    for (int r = 0; r < 16; ++r) {
        const float4* row = (const float4*)(base + (16 * oh + r) * 256 + 16 * ow);
#pragma unroll
        for (int j = 0; j < 4; ++j) {
            float4 v = row[j];
            m = fmaxf(m, fmaxf(fmaxf(v.x, v.y), fmaxf(v.z, v.w)));
        }
    }
    g_P4[b * 256 + t] = m;
}

// ---------------------------------------------------------------------------
// Kernel 1: T3[b, j, hw] = maxpool8(x3[b,j]) + P4[b, hw]   (x3: [2,256,128,128])
// grid = 512 blocks (b*256 + j), 256 threads
// ---------------------------------------------------------------------------
__global__ void pool_x3_kernel(const float* __restrict__ x3) {
    const int B  = blockIdx.x;
    const int b  = B >> 8, j = B & 255;
    const int t  = threadIdx.x;
    const int oh = t >> 4, ow = t & 15;
    const float* base = x3 + ((size_t)b * 256 + j) * 16384;
    float m = -CUDART_INF_F;
#pragma unroll
    for (int r = 0; r < 8; ++r) {
        const float4* row = (const float4*)(base + (8 * oh + r) * 128 + 8 * ow);
        float4 v0 = row[0];
        float4 v1 = row[1];
        m = fmaxf(m, fmaxf(fmaxf(v0.x, v0.y), fmaxf(v0.z, v0.w)));
        m = fmaxf(m, fmaxf(fmaxf(v1.x, v1.y), fmaxf(v1.z, v1.w)));
    }
    g_T3[((size_t)b * 256 + j) * 256 + t] = m + g_P4[b * 256 + t];
}

// ---------------------------------------------------------------------------
// Kernel 2 (fused main): one block per (b, k), k in [0,4096).
//   base = maxpool4(x2[b,k]) + T3[b, k%256]
//   for m in 0..3:  c = k + 4096*m
//     s = base + maxpool2(x1[b,c])
//     out[b,c]        = relu(s + ff[b,c])
//     out[b,c+16384]  = relu(s + ff[b,c+16384])
// x1: [2,16384,32,32], x2: [2,4096,64,64], ff/out: [2,32768,16,16]
// Every HBM byte of x1/x2/ff touched exactly once; T3 served from L2.
// ---------------------------------------------------------------------------
__global__ void fused_main_kernel(const float* __restrict__ x1,
                                  const float* __restrict__ x2,
                                  const float* __restrict__ ff,
                                  float* __restrict__ out) {
    const int B  = blockIdx.x;           // [0, 8192)
    const int b  = B >> 12, k = B & 4095;
    const int t  = threadIdx.x;          // [0, 256)
    const int oh = t >> 4, ow = t & 15;

    // maxpool4 of x2[b,k]: 4 rows x float4, fully coalesced across the warp
    const float* x2p = x2 + ((size_t)b * 4096 + k) * 4096;
    float p2 = -CUDART_INF_F;
#pragma unroll
    for (int r = 0; r < 4; ++r) {
        float4 v = *(const float4*)(x2p + (4 * oh + r) * 64 + 4 * ow);
        p2 = fmaxf(p2, fmaxf(fmaxf(v.x, v.y), fmaxf(v.z, v.w)));
    }

    const float basev = p2 + g_T3[((size_t)b * 256 + (k & 255)) * 256 + t];

#pragma unroll
    for (int m = 0; m < 4; ++m) {
        const int c = k + 4096 * m;
        // maxpool2 of x1[b,c]: two float2 loads per thread, coalesced
        const float* x1p = x1 + ((size_t)b * 16384 + c) * 1024;
        float2 a0 = *(const float2*)(x1p + (2 * oh)     * 32 + 2 * ow);
        float2 a1 = *(const float2*)(x1p + (2 * oh + 1) * 32 + 2 * ow);
        const float p1 = fmaxf(fmaxf(a0.x, a0.y), fmaxf(a1.x, a1.y));
        const float s  = basev + p1;

        const size_t o0 = ((size_t)b * 32768 + c) * 256 + t;
        const size_t o1 = o0 + (size_t)16384 * 256;
        out[o0] = fmaxf(s + ff[o0], 0.0f);
        out[o1] = fmaxf(s + ff[o1], 0.0f);
    }
}

// ---------------------------------------------------------------------------
// Launch: inputs in metadata order: x1, x2, x3, x4, pure_ff
// ---------------------------------------------------------------------------
extern "C" void kernel_launch(void* const* d_in, const int* in_sizes, int n_in,
                              void* d_out, int out_size) {
    const float* x1 = (const float*)d_in[0];
    const float* x2 = (const float*)d_in[1];
    const float* x3 = (const float*)d_in[2];
    const float* x4 = (const float*)d_in[3];
    const float* ff = (const float*)d_in[4];
    float* out = (float*)d_out;

    pool_x4_kernel<<<2, 256>>>(x4);
    pool_x3_kernel<<<512, 256>>>(x3);
    fused_main_kernel<<<8192, 256>>>(x1, x2, ff, out);
}

// round 2
// speedup vs baseline: 1.1117x; 1.1117x over previous
#include <cuda_runtime.h>
#include <math_constants.h>

// Scratch (no dynamic allocation allowed).
__device__ float g_P4[2 * 256];          // maxpool16(x4)           [b, hw]
__device__ float g_T3[2 * 256 * 256];    // maxpool8(x3)            [b, j, hw]

// ---------------------------------------------------------------------------
// Combined prologue kernel, grid = 1024 blocks x 256 threads.
//   Blocks [0, 512):    T3[b, j, hw] = maxpool8(x3[b,j])     (x3: [2,256,128,128])
//   Blocks [512, 1024): P4[b, hw]    = maxpool16(x4[b,0])    (x4: [2,1,256,256])
//                       one block per output value; 256-thread tree reduction
// The two halves are independent -> no serialization, pool4 latency hides
// under the 32 MB x3 read.
// ---------------------------------------------------------------------------
__global__ void prologue_kernel(const float* __restrict__ x3,
                                const float* __restrict__ x4) {
    const int B = blockIdx.x;
    const int t = threadIdx.x;

    if (B < 512) {
        // ---- maxpool8 of one x3 plane ----
        const int b  = B >> 8, j = B & 255;
        const int oh = t >> 4, ow = t & 15;
        const float* base = x3 + ((size_t)b * 256 + j) * 16384;
        float m = -CUDART_INF_F;
#pragma unroll
        for (int r = 0; r < 8; ++r) {
            const float4* row = (const float4*)(base + (8 * oh + r) * 128 + 8 * ow);
            float4 v0 = row[0];
            float4 v1 = row[1];
            m = fmaxf(m, fmaxf(fmaxf(v0.x, v0.y), fmaxf(v0.z, v0.w)));
            m = fmaxf(m, fmaxf(fmaxf(v1.x, v1.y), fmaxf(v1.z, v1.w)));
        }
        g_T3[((size_t)b * 256 + j) * 256 + t] = m;
    } else {
        // ---- maxpool16 of x4: one output value per block ----
        const int o  = B - 512;            // [0, 512)
        const int b  = o >> 8;
        const int p  = o & 255;            // output pixel index
        const int oh = p >> 4, ow = p & 15;
        // thread t reads one element of the 16x16 window:
        //   row = t/16, col = t%16  -> 16 consecutive floats per 16-thread group
        const float* base = x4 + (size_t)b * 65536;
        float v = base[(16 * oh + (t >> 4)) * 256 + 16 * ow + (t & 15)];

        // block-wide max reduction
        __shared__ float red[8];
#pragma unroll
        for (int s = 16; s > 0; s >>= 1)
            v = fmaxf(v, __shfl_down_sync(0xFFFFFFFFu, v, s));
        if ((t & 31) == 0) red[t >> 5] = v;
        __syncthreads();
        if (t == 0) {
            float m = red[0];
#pragma unroll
            for (int w = 1; w < 8; ++w) m = fmaxf(m, red[w]);
            g_P4[b * 256 + p] = m;
        }
    }
}

// ---------------------------------------------------------------------------
// Fused main kernel: one block per (b, k), k in [0,4096).
//   base = maxpool4(x2[b,k]) + T3[b, k%256, t] + P4[b, t]
//   for m in 0..3:  c = k + 4096*m
//     s = base + maxpool2(x1[b,c])
//     out[b,c]        = relu(s + ff[b,c])
//     out[b,c+16384]  = relu(s + ff[b,c+16384])
// x1: [2,16384,32,32], x2: [2,4096,64,64], ff/out: [2,32768,16,16]
// Every HBM byte of x1/x2/ff touched exactly once; T3/P4 served from L2.
// ---------------------------------------------------------------------------
__global__ void fused_main_kernel(const float* __restrict__ x1,
                                  const float* __restrict__ x2,
                                  const float* __restrict__ ff,
                                  float* __restrict__ out) {
    const int B  = blockIdx.x;           // [0, 8192)
    const int b  = B >> 12, k = B & 4095;
    const int t  = threadIdx.x;          // [0, 256)
    const int oh = t >> 4, ow = t & 15;

    // maxpool4 of x2[b,k]: 4 rows x float4, fully coalesced across the warp
    const float* x2p = x2 + ((size_t)b * 4096 + k) * 4096;
    float p2 = -CUDART_INF_F;
#pragma unroll
    for (int r = 0; r < 4; ++r) {
        float4 v = *(const float4*)(x2p + (4 * oh + r) * 64 + 4 * ow);
        p2 = fmaxf(p2, fmaxf(fmaxf(v.x, v.y), fmaxf(v.z, v.w)));
    }

    const float basev = p2
                      + g_T3[((size_t)b * 256 + (k & 255)) * 256 + t]
                      + g_P4[b * 256 + t];

#pragma unroll
    for (int m = 0; m < 4; ++m) {
        const int c = k + 4096 * m;
        // maxpool2 of x1[b,c]: two float2 loads per thread, coalesced
        const float* x1p = x1 + ((size_t)b * 16384 + c) * 1024;
        float2 a0 = *(const float2*)(x1p + (2 * oh)     * 32 + 2 * ow);
        float2 a1 = *(const float2*)(x1p + (2 * oh + 1) * 32 + 2 * ow);
        const float p1 = fmaxf(fmaxf(a0.x, a0.y), fmaxf(a1.x, a1.y));
        const float s  = basev + p1;

        const size_t o0 = ((size_t)b * 32768 + c) * 256 + t;
        const size_t o1 = o0 + (size_t)16384 * 256;
        out[o0] = fmaxf(s + ff[o0], 0.0f);
        out[o1] = fmaxf(s + ff[o1], 0.0f);
    }
}

// ---------------------------------------------------------------------------
// Launch: inputs in metadata order: x1, x2, x3, x4, pure_ff
// ---------------------------------------------------------------------------
extern "C" void kernel_launch(void* const* d_in, const int* in_sizes, int n_in,
                              void* d_out, int out_size) {
    const float* x1 = (const float*)d_in[0];
    const float* x2 = (const float*)d_in[1];
    const float* x3 = (const float*)d_in[2];
    const float* x4 = (const float*)d_in[3];
    const float* ff = (const float*)d_in[4];
    float* out = (float*)d_out;

    prologue_kernel<<<1024, 256>>>(x3, x4);
    fused_main_kernel<<<8192, 256>>>(x1, x2, ff, out);
}

// round 3
// speedup vs baseline: 1.1267x; 1.0135x over previous
#include <cuda_runtime.h>
#include <math_constants.h>

// Scratch (no dynamic allocation allowed).
__device__ float g_P4[2 * 256];          // maxpool16(x4)  [b, hw]
__device__ float g_T3[2 * 256 * 256];    // maxpool8(x3)   [b, j, hw]

// ---------------------------------------------------------------------------
// Prologue kernel, grid = 1024 x 256. Fires the PDL trigger immediately so the
// main kernel launches concurrently and overlaps its x1/x2 reads with ours.
//   Blocks [0, 512):    T3[b, j, hw] = maxpool8(x3[b,j])   (x3: [2,256,128,128])
//   Blocks [512, 1024): P4[b, hw]    = maxpool16(x4[b,0])  (x4: [2,1,256,256])
// ---------------------------------------------------------------------------
__global__ void prologue_kernel(const float* __restrict__ x3,
                                const float* __restrict__ x4) {
#if __CUDA_ARCH__ >= 900
    cudaTriggerProgrammaticLaunchCompletion();
#endif
    const int B = blockIdx.x;
    const int t = threadIdx.x;

    if (B < 512) {
        // ---- maxpool8 of one x3 plane ----
        const int b  = B >> 8, j = B & 255;
        const int oh = t >> 4, ow = t & 15;
        const float* base = x3 + ((size_t)b * 256 + j) * 16384;
        float m = -CUDART_INF_F;
#pragma unroll
        for (int r = 0; r < 8; ++r) {
            const float4* row = (const float4*)(base + (8 * oh + r) * 128 + 8 * ow);
            float4 v0 = row[0];
            float4 v1 = row[1];
            m = fmaxf(m, fmaxf(fmaxf(v0.x, v0.y), fmaxf(v0.z, v0.w)));
            m = fmaxf(m, fmaxf(fmaxf(v1.x, v1.y), fmaxf(v1.z, v1.w)));
        }
        g_T3[((size_t)b * 256 + j) * 256 + t] = m;
    } else {
        // ---- maxpool16 of x4: one output value per block, tree reduction ----
        const int o  = B - 512;            // [0, 512)
        const int b  = o >> 8;
        const int p  = o & 255;            // output pixel index
        const int oh = p >> 4, ow = p & 15;
        const float* base = x4 + (size_t)b * 65536;
        float v = base[(16 * oh + (t >> 4)) * 256 + 16 * ow + (t & 15)];

        __shared__ float red[8];
#pragma unroll
        for (int s = 16; s > 0; s >>= 1)
            v = fmaxf(v, __shfl_down_sync(0xFFFFFFFFu, v, s));
        if ((t & 31) == 0) red[t >> 5] = v;
        __syncthreads();
        if (t == 0) {
            float m = red[0];
#pragma unroll
            for (int w = 1; w < 8; ++w) m = fmaxf(m, red[w]);
            g_P4[b * 256 + p] = m;
        }
    }
}

// ---------------------------------------------------------------------------
// Fused main kernel: one block per (b, k), k in [0,4096).
// Launched with PROGRAMMATIC_STREAM_SERIALIZATION: it starts while the
// prologue is still running. All x2/x1 HBM reads are issued and reduced to
// registers BEFORE cudaGridDependencySynchronize(); only the T3/P4 adds and
// the ff/out streaming happen after.
//   base = maxpool4(x2[b,k]) + T3[b, k%256, t] + P4[b, t]
//   for m in 0..3:  c = k + 4096*m
//     s = base + maxpool2(x1[b,c])
//     out[b,c]        = relu(s + ff[b,c])
//     out[b,c+16384]  = relu(s + ff[b,c+16384])
// ---------------------------------------------------------------------------
__global__ void fused_main_kernel(const float* __restrict__ x1,
                                  const float* __restrict__ x2,
                                  const float* __restrict__ ff,
                                  float* __restrict__ out) {
    const int B  = blockIdx.x;           // [0, 8192)
    const int b  = B >> 12, k = B & 4095;
    const int t  = threadIdx.x;          // [0, 256)
    const int oh = t >> 4, ow = t & 15;

    // ---- prologue-independent reads: x2 pool4 ----
    const float* x2p = x2 + ((size_t)b * 4096 + k) * 4096;
    float p2 = -CUDART_INF_F;
#pragma unroll
    for (int r = 0; r < 4; ++r) {
        float4 v = *(const float4*)(x2p + (4 * oh + r) * 64 + 4 * ow);
        p2 = fmaxf(p2, fmaxf(fmaxf(v.x, v.y), fmaxf(v.z, v.w)));
    }

    // ---- prologue-independent reads: x1 pool2 for all 4 aliases ----
    float p1v[4];
#pragma unroll
    for (int m = 0; m < 4; ++m) {
        const int c = k + 4096 * m;
        const float* x1p = x1 + ((size_t)b * 16384 + c) * 1024;
        float2 a0 = *(const float2*)(x1p + (2 * oh)     * 32 + 2 * ow);
        float2 a1 = *(const float2*)(x1p + (2 * oh + 1) * 32 + 2 * ow);
        p1v[m] = fmaxf(fmaxf(a0.x, a0.y), fmaxf(a1.x, a1.y));
    }

    // ---- wait for prologue grid (T3, P4 visible) ----
#if __CUDA_ARCH__ >= 900
    cudaGridDependencySynchronize();
#endif

    const float basev = p2
                      + g_T3[((size_t)b * 256 + (k & 255)) * 256 + t]
                      + g_P4[b * 256 + t];

#pragma unroll
    for (int m = 0; m < 4; ++m) {
        const int c = k + 4096 * m;
        const float s = basev + p1v[m];
        const size_t o0 = ((size_t)b * 32768 + c) * 256 + t;
        const size_t o1 = o0 + (size_t)16384 * 256;
        out[o0] = fmaxf(s + ff[o0], 0.0f);
        out[o1] = fmaxf(s + ff[o1], 0.0f);
    }
}

// ---------------------------------------------------------------------------
// Launch: inputs in metadata order: x1, x2, x3, x4, pure_ff
// ---------------------------------------------------------------------------
extern "C" void kernel_launch(void* const* d_in, const int* in_sizes, int n_in,
                              void* d_out, int out_size) {
    const float* x1 = (const float*)d_in[0];
    const float* x2 = (const float*)d_in[1];
    const float* x3 = (const float*)d_in[2];
    const float* x4 = (const float*)d_in[3];
    const float* ff = (const float*)d_in[4];
    float* out = (float*)d_out;

    prologue_kernel<<<1024, 256>>>(x3, x4);

    cudaLaunchConfig_t cfg = {};
    cfg.gridDim  = dim3(8192, 1, 1);
    cfg.blockDim = dim3(256, 1, 1);
    cfg.dynamicSmemBytes = 0;
    cfg.stream = 0;
    cudaLaunchAttribute attrs[1];
    attrs[0].id = cudaLaunchAttributeProgrammaticStreamSerialization;
    attrs[0].val.programmaticStreamSerializationAllowed = 1;
    cfg.attrs = attrs;
    cfg.numAttrs = 1;
    cudaLaunchKernelEx(&cfg, fused_main_kernel, x1, x2, ff, out);
}